// round 14
// baseline (speedup 1.0000x reference)
#include <cuda_runtime.h>
#include <math.h>

#define BB 8
#define VV 3
#define HH 512
#define WW 640
#define NPIX (HH*WW)
#define NPAIR (VV*VV)
#define TPB 256
#define NWARP (TPB/32)
#define GX 64
#define STRIDE (GX*TPB)            // 16384 = 25*640 + 384 ; NPIX/STRIDE = 20 exact
#define NPASS (NPIX/STRIDE)        // 20, uniform for every thread
#define NBLOCKS (GX*BB*NPAIR)

#define FMAGIC 8388610.0f          // 2^23 + 2
#define IMAGIC 0x4B000002

__device__ double   g_num[BB*NPAIR];
__device__ double   g_den[BB*NPAIR];
__device__ unsigned g_count;

__device__ __forceinline__ void mat4mul(const float* A, const float* Bm, float* C) {
#pragma unroll
    for (int r = 0; r < 4; r++)
#pragma unroll
        for (int c = 0; c < 4; c++) {
            float s = 0.0f;
#pragma unroll
            for (int k = 0; k < 4; k++) s = fmaf(A[r*4+k], Bm[k*4+c], s);
            C[r*4+c] = s;
        }
}

__device__ __forceinline__ void compute_P(const float* __restrict__ K,
                                          const float* __restrict__ RT,
                                          int b, int i, int j, float* out) {
    const float* Kb  = K  + b*16;
    const float* RTi = RT + (b*VV + i)*16;
    const float* RTj = RT + (b*VV + j)*16;

    float Kinv[16] = {0};
    float fx = Kb[0], fy = Kb[5], cx = Kb[2], cy = Kb[6];
    Kinv[0]  = 1.0f/fx;  Kinv[2]  = -cx/fx;
    Kinv[5]  = 1.0f/fy;  Kinv[6]  = -cy/fy;
    Kinv[10] = 1.0f;     Kinv[15] = 1.0f;

    float Ri[16] = {0};
    Ri[0] = RTi[0]; Ri[1] = RTi[4]; Ri[2]  = RTi[8];
    Ri[4] = RTi[1]; Ri[5] = RTi[5]; Ri[6]  = RTi[9];
    Ri[8] = RTi[2]; Ri[9] = RTi[6]; Ri[10] = RTi[10];
    float tx = RTi[3], ty = RTi[7], tz = RTi[11];
    Ri[3]  = -(Ri[0]*tx + Ri[1]*ty + Ri[2]*tz);
    Ri[7]  = -(Ri[4]*tx + Ri[5]*ty + Ri[6]*tz);
    Ri[11] = -(Ri[8]*tx + Ri[9]*ty + Ri[10]*tz);
    Ri[15] = 1.0f;

    float M1[16], M2[16], Pf[16];
    mat4mul(RTj, Ri, M1);
    mat4mul(M1, Kinv, M2);
    mat4mul(Kb, M2, Pf);
#pragma unroll
    for (int k = 0; k < 12; k++) out[k] = Pf[k];
}

// Dense gather + bilinear for one compacted item (px,py,pz). Item guaranteed in-bounds.
__device__ __forceinline__ float process_item(const float4 it,
                                              const float* __restrict__ dj) {
    const float SXI = 640.0f/639.0f, SYI = 512.0f/511.0f;
    const float px = it.x, py = it.y, pz = it.z;
    const float ux = fmaf(px, SXI, -1.0f);   // ix - 0.5
    const float uy = fmaf(py, SYI, -1.0f);
    const float tmx = ux + FMAGIC;
    const float tmy = uy + FMAGIC;
    const int   x0 = __float_as_int(tmx) - IMAGIC;   // floor(ix) in [-1, 639]
    const int   y0 = __float_as_int(tmy) - IMAGIC;   // floor(iy) in [-1, 511]
    const float x0f = tmx - FMAGIC;
    const float y0f = tmy - FMAGIC;
    const float wx1 = (ux - x0f) + 0.5f;
    const float wy1 = (uy - y0f) + 0.5f;
    const int base = y0*WW + x0;
    const bool vx0 = (x0 >= 0);
    const bool vx1 = (x0 < WW-1);
    const bool vy0 = (y0 >= 0);
    const bool vy1 = (y0 < HH-1);
    const float c00 = (vx0 && vy0) ? __ldg(dj + base)        : 0.0f;
    const float c10 = (vx1 && vy0) ? __ldg(dj + base + 1)    : 0.0f;
    const float c01 = (vx0 && vy1) ? __ldg(dj + base + WW)   : 0.0f;
    const float c11 = (vx1 && vy1) ? __ldg(dj + base + WW+1) : 0.0f;
    const float top = fmaf(wx1, c10 - c00, c00);
    const float bot = fmaf(wx1, c11 - c01, c01);
    const float warped = fmaf(wy1, bot - top, top);
    return fabsf(warped - pz);
}

__global__ void __launch_bounds__(TPB, 6)
loss_kernel(const float* __restrict__ pred, const float* __restrict__ K,
            const float* __restrict__ RT, float* __restrict__ out) {
    const int b = blockIdx.y, p = blockIdx.z;
    const int i = p / VV, j = p - (p / VV)*VV;

    __shared__ float  sP[12];
    __shared__ float4 sbuf[NWARP][64];
    if (threadIdx.x == 0)
        compute_P(K, RT, b, i, j, sP);
    __syncthreads();

    const float* __restrict__ di = pred + (size_t)(b*VV + i)*NPIX;
    const float* __restrict__ dj = pred + (size_t)(b*VV + j)*NPIX;

    const float P00 = sP[0], P01 = sP[1], P02 = sP[2],  P03 = sP[3];
    const float P10 = sP[4], P11 = sP[5], P12 = sP[6],  P13 = sP[7];
    const float P20 = sP[8], P21 = sP[9], P22 = sP[10], P23 = sP[11];

    const unsigned XB = __float_as_uint(639.0f);
    const unsigned YB = __float_as_uint(511.0f);

    const int lane = threadIdx.x & 31, warp = threadIdx.x >> 5;
    const unsigned lmlt = (1u << lane) - 1u;

    const int n0 = blockIdx.x*TPB + threadIdx.x;
    int yy = n0 / (WW/4*4);        // n0 / 640
    yy = n0 / WW;
    float yf = (float)yy;
    float xf = (float)(n0 - yy*WW);

    float lnum = 0.0f, lden = 0.0f;
    int wcount = 0, whead = 0;     // uniform across warp

#pragma unroll 4
    for (int pass = 0; pass < NPASS; pass++) {
        const int n = n0 + pass*STRIDE;
        const float d = __ldg(di + n);

        const float ax = fmaf(P00, xf, fmaf(P01, yf, P02));
        const float ay = fmaf(P10, xf, fmaf(P11, yf, P12));
        const float az = fmaf(P20, xf, fmaf(P21, yf, P22));
        const float px = fmaf(d, ax, P03);   // homogeneous w == 1 exactly
        const float py = fmaf(d, ay, P13);
        const float pz = fmaf(d, az, P23);

        // in-bounds: px in [0,639] && py in [0,511] via unsigned-int compare
        const bool in = (__float_as_uint(px) <= XB) && (__float_as_uint(py) <= YB);
        lden += in ? 1.0f : 0.0f;

        const unsigned m = __ballot_sync(0xFFFFFFFFu, in);
        if (m) {
            const int pos = wcount + __popc(m & lmlt);
            if (in) sbuf[warp][pos & 63] = make_float4(px, py, pz, 0.0f);
            wcount += __popc(m);
            if (wcount - whead >= 32) {
                const float4 it = sbuf[warp][(whead + lane) & 63];
                whead += 32;
                lnum += process_item(it, dj);
            }
        }

        // advance: STRIDE = 25*640 + 384
        xf += 384.0f;
        if (xf >= 640.0f) { xf -= 640.0f; yf += 26.0f; }
        else              { yf += 25.0f; }
    }

    // drain remaining items (< 32)
    {
        const int rem = wcount - whead;
        if (lane < rem) {
            const float4 it = sbuf[warp][(whead + lane) & 63];
            lnum += process_item(it, dj);
        }
    }

    // block reduce
    __shared__ float snum[NWARP], sden[NWARP];
#pragma unroll
    for (int o = 16; o > 0; o >>= 1) {
        lnum += __shfl_xor_sync(0xFFFFFFFFu, lnum, o);
        lden += __shfl_xor_sync(0xFFFFFFFFu, lden, o);
    }
    if (lane == 0) { snum[warp] = lnum; sden[warp] = lden; }
    __syncthreads();
    if (threadIdx.x < 2) {
        const float* src = threadIdx.x ? sden : snum;
        float s = 0.0f;
#pragma unroll
        for (int w = 0; w < NWARP; w++) s += src[w];
        const int pg = b*NPAIR + p;
        if (threadIdx.x == 0) atomicAdd(&g_num[pg], (double)s);
        else                  atomicAdd(&g_den[pg], (double)s);
    }
    __syncthreads();

    // last-block finalize
    __shared__ bool s_last;
    if (threadIdx.x == 0) {
        __threadfence();
        s_last = (atomicAdd(&g_count, 1u) == (unsigned)(NBLOCKS - 1));
    }
    __syncthreads();
    if (s_last && threadIdx.x == 0) {
        double t = 0.0;
#pragma unroll
        for (int pp = 0; pp < NPAIR; pp++) {
            double n = 0.0, dn = 0.0;
#pragma unroll
            for (int bb = 0; bb < BB; bb++) {
                n  += g_num[bb*NPAIR + pp];
                dn += g_den[bb*NPAIR + pp];
            }
            t += n / (dn > 1.0 ? dn : 1.0);
        }
        out[0] = (float)t;
#pragma unroll
        for (int pp = 0; pp < BB*NPAIR; pp++) { g_num[pp] = 0.0; g_den[pp] = 0.0; }
        __threadfence();
        g_count = 0u;
    }
}

extern "C" void kernel_launch(void* const* d_in, const int* in_sizes, int n_in,
                              void* d_out, int out_size) {
    const float* pred = (const float*)d_in[0];   // (B,V,H,W)
    const float* K    = (const float*)d_in[1];   // (B,4,4)
    const float* RT   = (const float*)d_in[2];   // (B,V,4,4)
    loss_kernel<<<dim3(GX, BB, NPAIR), TPB>>>(pred, K, RT, (float*)d_out);
}